// round 10
// baseline (speedup 1.0000x reference)
#include <cuda_runtime.h>
#include <cuda_fp16.h>
#include <cstdint>

// ============================================================================
// C[8192,1024] = A[8192,4096] @ B[1024,4096]^T   (fp32 in/out)
//
// Base sm_103 (no tcgen05). fp16 mma.sync.m16n8k16 (rel_err 2.9e-4).
// R9: R7 champion GEMM split along M into 2 independent halves; the
// second half's A-conversion runs on a side stream under the first
// half's GEMM. No accumulation, no RMW, full-K passes (R8 lesson).
// ============================================================================

static constexpr int M_TOTAL = 8192;
static constexpr int K_DIM   = 4096;
static constexpr int N_TOTAL = 1024;

static constexpr int BM = 128;
static constexpr int BN = 128;
static constexpr int BK = 64;
static constexpr int STAGES = 3;
static constexpr int NK = K_DIM / BK;  // 64

static constexpr int TILE_BYTES  = BM * BK * 2;          // 16384
static constexpr int STAGE_BYTES = 2 * TILE_BYTES;       // 32768
static constexpr int SMEM_TOTAL  = STAGES * STAGE_BYTES; // 98304 -> 2 CTAs/SM

// M split: half0 = 3072 rows (24 m-tiles), half1 = 5120 rows (40 m-tiles)
static constexpr int MT0 = 24;
static constexpr int MT1 = 40;

// --------------------------------------------------------------------------
// Static scratch: fp16 copies of A and B
// --------------------------------------------------------------------------
__device__ __half g_Ah[(size_t)M_TOTAL * K_DIM];
__device__ __half g_Bh[(size_t)N_TOTAL * K_DIM];

static constexpr int NB4 = (N_TOTAL * K_DIM) / 4;

// --------------------------------------------------------------------------
// Converters (fp32 -> fp16, 4-wide)
// --------------------------------------------------------------------------
__device__ __forceinline__ uint2 cvt4(float4 v) {
    __half2 lo = __floats2half2_rn(v.x, v.y);
    __half2 hi = __floats2half2_rn(v.z, v.w);
    return make_uint2(*reinterpret_cast<uint32_t*>(&lo), *reinterpret_cast<uint32_t*>(&hi));
}

__global__ void __launch_bounds__(256)
cvt_b_kernel(const float4* __restrict__ B, uint2* __restrict__ Bh) {
    int i = blockIdx.x * blockDim.x + threadIdx.x;
    if (i < NB4) Bh[i] = cvt4(B[i]);
}

// Converts A rows [base4, base4+n4) in float4 units (rows are contiguous).
__global__ void __launch_bounds__(256)
cvt_a_rows_kernel(const float4* __restrict__ A, uint2* __restrict__ Ah,
                  int base4, int n4) {
    int i = blockIdx.x * blockDim.x + threadIdx.x;
    if (i < n4) Ah[base4 + i] = cvt4(A[base4 + i]);
}

// --------------------------------------------------------------------------
// PTX helpers
// --------------------------------------------------------------------------
__device__ __forceinline__ void cp_async16(uint32_t saddr, const void* gptr) {
    asm volatile("cp.async.cg.shared.global [%0], [%1], 16;"
                 :: "r"(saddr), "l"(__cvta_generic_to_global(gptr)) : "memory");
}

#define CP_COMMIT() asm volatile("cp.async.commit_group;" ::: "memory")
#define CP_WAIT(N)  asm volatile("cp.async.wait_group %0;" :: "n"(N) : "memory")

#define LDSM_X4(R, addr)                                                     \
    asm volatile("ldmatrix.sync.aligned.m8n8.x4.shared.b16 {%0,%1,%2,%3}, [%4];" \
                 : "=r"((R)[0]), "=r"((R)[1]), "=r"((R)[2]), "=r"((R)[3])    \
                 : "r"(addr))

#define MMA_F16(C, A, B0, B1)                                                \
    asm volatile("mma.sync.aligned.m16n8k16.row.col.f32.f16.f16.f32 "        \
                 "{%0,%1,%2,%3}, {%4,%5,%6,%7}, {%8,%9}, {%0,%1,%2,%3};"     \
                 : "+f"((C)[0]), "+f"((C)[1]), "+f"((C)[2]), "+f"((C)[3])    \
                 : "r"((A)[0]), "r"((A)[1]), "r"((A)[2]), "r"((A)[3]),       \
                   "r"(B0), "r"(B1))

__device__ __forceinline__ uint32_t swz(int row, int col_bytes) {
    return (uint32_t)(row * 128 + (col_bytes ^ ((row & 7) * 16)));
}

// --------------------------------------------------------------------------
// GEMM over m-tiles [mt0, mt0+grid/8): R7 champion structure, full K.
// --------------------------------------------------------------------------
__global__ void __launch_bounds__(256, 2)
gemm_f16_kernel(float* __restrict__ C, int mt0) {
    extern __shared__ uint8_t smem[];
    const uint32_t sbase = (uint32_t)__cvta_generic_to_shared(smem);

    const int tid  = threadIdx.x;
    const int lane = tid & 31;
    const int wid  = tid >> 5;
    const int wm   = (wid & 3) * 32;
    const int wn   = (wid >> 2) * 64;

    const int m0 = (mt0 + (blockIdx.x >> 3)) * BM;   // octet shares A in L2
    const int n0 = (blockIdx.x & 7) * BN;

    auto load_stage = [&](int s, int kt) {
        const uint32_t st = sbase + s * STAGE_BYTES;
        const int kbase = kt * BK;
        #pragma unroll
        for (int i = 0; i < 4; i++) {
            const int idx = tid + i * 256;
            const int row = idx >> 3;
            const int ch  = idx & 7;
            const uint32_t soff = swz(row, ch * 16);
            cp_async16(st +              soff, &g_Ah[(size_t)(m0 + row) * K_DIM + kbase + ch * 8]);
            cp_async16(st + TILE_BYTES + soff, &g_Bh[(size_t)(n0 + row) * K_DIM + kbase + ch * 8]);
        }
    };

    int a_row[2], a_xor[2];
    #pragma unroll
    for (int m = 0; m < 2; m++) {
        const int r = wm + m * 16 + (lane & 15);
        a_row[m] = r * 128;
        a_xor[m] = (r & 7) * 16;
    }
    const int a_colb = (lane >> 4) * 16;
    int b_row[4], b_xor[4];
    #pragma unroll
    for (int p = 0; p < 4; p++) {
        const int r = wn + p * 16 + (lane & 7) + ((lane >> 4) << 3);
        b_row[p] = r * 128;
        b_xor[p] = (r & 7) * 16;
    }
    const int b_colb = ((lane >> 3) & 1) * 16;

    auto lds_frags = [&](uint32_t st, int ks, uint32_t (&a)[2][4], uint32_t (&b)[4][4]) {
        const int kb = ks * 32;
        #pragma unroll
        for (int m = 0; m < 2; m++)
            LDSM_X4(a[m], st + a_row[m] + ((kb + a_colb) ^ a_xor[m]));
        #pragma unroll
        for (int p = 0; p < 4; p++)
            LDSM_X4(b[p], st + TILE_BYTES + b_row[p] + ((kb + b_colb) ^ b_xor[p]));
    };

    float acc[2][8][4];
    #pragma unroll
    for (int m = 0; m < 2; m++)
        #pragma unroll
        for (int n = 0; n < 8; n++)
            #pragma unroll
            for (int q = 0; q < 4; q++) acc[m][n][q] = 0.f;

    load_stage(0, 0); CP_COMMIT();
    load_stage(1, 1); CP_COMMIT();

    uint32_t af[2][2][4], bf[2][4][4];

    for (int kt = 0; kt < NK; kt++) {
        if (kt < NK - 1) { CP_WAIT(1); } else { CP_WAIT(0); }
        __syncthreads();
        if (kt + 2 < NK) {
            load_stage((kt + 2) % STAGES, kt + 2);
            CP_COMMIT();
        }

        const uint32_t st = sbase + (kt % STAGES) * STAGE_BYTES;

        lds_frags(st, 0, af[0], bf[0]);
        #pragma unroll
        for (int ks = 0; ks < 4; ks++) {
            const int cur = ks & 1;
            if (ks < 3)
                lds_frags(st, ks + 1, af[cur ^ 1], bf[cur ^ 1]);
            #pragma unroll
            for (int m = 0; m < 2; m++)
                #pragma unroll
                for (int p = 0; p < 4; p++)
                    #pragma unroll
                    for (int q = 0; q < 2; q++)
                        MMA_F16(acc[m][2 * p + q], af[cur][m],
                                bf[cur][p][2 * q], bf[cur][p][2 * q + 1]);
        }
    }

    // ---- epilogue: direct STG.64 ----
    #pragma unroll
    for (int m = 0; m < 2; m++) {
        const int r0 = m0 + wm + m * 16 + (lane >> 2);
        #pragma unroll
        for (int n = 0; n < 8; n++) {
            const int col = n0 + wn + n * 8 + (lane & 3) * 2;
            float2* q0 = reinterpret_cast<float2*>(&C[(size_t)r0 * N_TOTAL + col]);
            float2* q1 = reinterpret_cast<float2*>(&C[(size_t)(r0 + 8) * N_TOTAL + col]);
            *q0 = make_float2(acc[m][n][0], acc[m][n][1]);
            *q1 = make_float2(acc[m][n][2], acc[m][n][3]);
        }
    }
}

// --------------------------------------------------------------------------
// Launch: M-split overlap. Half-1's cvt hides under half-0's GEMM; the two
// GEMMs are independent (disjoint C rows) so half-1 backfills half-0's tail.
// --------------------------------------------------------------------------
extern "C" void kernel_launch(void* const* d_in, const int* in_sizes, int n_in,
                              void* d_out, int out_size) {
    const float* A = (const float*)d_in[0];   // [8192, 4096]
    const float* B = (const float*)d_in[1];   // [1024, 4096]
    float* C = (float*)d_out;                 // [8192, 1024]

    __half *aH, *bH;
    cudaGetSymbolAddress((void**)&aH, g_Ah);
    cudaGetSymbolAddress((void**)&bH, g_Bh);

    static cudaStream_t side = nullptr;
    static cudaEvent_t ev0 = nullptr, ev1 = nullptr;
    static bool init_done = false;
    if (!init_done) {
        cudaStreamCreateWithFlags(&side, cudaStreamNonBlocking);
        cudaEventCreateWithFlags(&ev0, cudaEventDisableTiming);
        cudaEventCreateWithFlags(&ev1, cudaEventDisableTiming);
        cudaFuncSetAttribute(gemm_f16_kernel,
                             cudaFuncAttributeMaxDynamicSharedMemorySize, SMEM_TOTAL);
        init_done = true;
    }

    const int rows0_f4 = MT0 * BM * (K_DIM / 4);           // half0 float4 count
    const int rows1_f4 = MT1 * BM * (K_DIM / 4);           // half1 float4 count

    // ---- serial head: B + A half0 ----
    cvt_b_kernel<<<(NB4 + 255) / 256, 256>>>((const float4*)B, (uint2*)bH);
    cvt_a_rows_kernel<<<(rows0_f4 + 255) / 256, 256>>>((const float4*)A, (uint2*)aH,
                                                       0, rows0_f4);
    cudaEventRecord(ev0, 0);

    // ---- fork: side stream converts A half1 under GEMM half0 ----
    cudaStreamWaitEvent(side, ev0, 0);
    cvt_a_rows_kernel<<<(rows1_f4 + 255) / 256, 256, 0, side>>>(
        (const float4*)A, (uint2*)aH, rows0_f4, rows1_f4);
    cudaEventRecord(ev1, side);

    // ---- main: GEMM half0 now; GEMM half1 gated only on its cvt ----
    gemm_f16_kernel<<<MT0 * 8, 256, SMEM_TOTAL>>>(C, 0);
    cudaStreamWaitEvent(0, ev1, 0);
    gemm_f16_kernel<<<MT1 * 8, 256, SMEM_TOTAL>>>(C, MT0);
}

// round 12
// speedup vs baseline: 1.2325x; 1.2325x over previous
#include <cuda_runtime.h>
#include <cuda_fp16.h>
#include <cstdint>

// ============================================================================
// C[8192,1024] = A[8192,4096] @ B[1024,4096]^T   (fp32 in/out)
//
// Base sm_103 (no tcgen05). fp16 mma.sync.m16n8k16 (rel_err 2.9e-4).
// R10: M-split overlap, CORRECTLY CONCURRENT this time:
//   main: [cvt B + A-half0] -> GEMM half0
//   side: wait -> cvt A-half1 -> GEMM half1   (runs concurrently with half0)
//   main: join on side-stream event (single graph sink).
// R9's bug was both GEMMs on one stream (serialized, 43% tensor).
// ============================================================================

static constexpr int M_TOTAL = 8192;
static constexpr int K_DIM   = 4096;
static constexpr int N_TOTAL = 1024;

static constexpr int BM = 128;
static constexpr int BN = 128;
static constexpr int BK = 64;
static constexpr int STAGES = 3;
static constexpr int NK = K_DIM / BK;  // 64

static constexpr int TILE_BYTES  = BM * BK * 2;          // 16384
static constexpr int STAGE_BYTES = 2 * TILE_BYTES;       // 32768
static constexpr int SMEM_TOTAL  = STAGES * STAGE_BYTES; // 98304 -> 2 CTAs/SM

// Even M split: 32 + 32 m-tiles
static constexpr int MT0 = 32;
static constexpr int MT1 = 32;

// --------------------------------------------------------------------------
// Static scratch: fp16 copies of A and B
// --------------------------------------------------------------------------
__device__ __half g_Ah[(size_t)M_TOTAL * K_DIM];
__device__ __half g_Bh[(size_t)N_TOTAL * K_DIM];

static constexpr int NB4    = (N_TOTAL * K_DIM) / 4;             // 1048576
static constexpr int NA0_F4 = MT0 * BM * (K_DIM / 4);            // half0 float4s
static constexpr int NA1_F4 = MT1 * BM * (K_DIM / 4);            // half1 float4s

// --------------------------------------------------------------------------
// Converters (fp32 -> fp16, 4-wide)
// --------------------------------------------------------------------------
__device__ __forceinline__ uint2 cvt4(float4 v) {
    __half2 lo = __floats2half2_rn(v.x, v.y);
    __half2 hi = __floats2half2_rn(v.z, v.w);
    return make_uint2(*reinterpret_cast<uint32_t*>(&lo), *reinterpret_cast<uint32_t*>(&hi));
}

// Head: B (NB4) then A half0 (NA0_F4) in one grid.
__global__ void __launch_bounds__(256)
cvt_head_kernel(const float4* __restrict__ A, const float4* __restrict__ B,
                uint2* __restrict__ Ah, uint2* __restrict__ Bh) {
    int i = blockIdx.x * blockDim.x + threadIdx.x;
    if (i < NB4) {
        Bh[i] = cvt4(B[i]);
    } else {
        i -= NB4;
        if (i >= NA0_F4) return;
        Ah[i] = cvt4(A[i]);
    }
}

// A half1: float4 indices [NA0_F4, NA0_F4 + NA1_F4)
__global__ void __launch_bounds__(256)
cvt_a1_kernel(const float4* __restrict__ A, uint2* __restrict__ Ah) {
    int i = blockIdx.x * blockDim.x + threadIdx.x;
    if (i < NA1_F4) Ah[NA0_F4 + i] = cvt4(A[NA0_F4 + i]);
}

// --------------------------------------------------------------------------
// PTX helpers
// --------------------------------------------------------------------------
__device__ __forceinline__ void cp_async16(uint32_t saddr, const void* gptr) {
    asm volatile("cp.async.cg.shared.global [%0], [%1], 16;"
                 :: "r"(saddr), "l"(__cvta_generic_to_global(gptr)) : "memory");
}

#define CP_COMMIT() asm volatile("cp.async.commit_group;" ::: "memory")
#define CP_WAIT(N)  asm volatile("cp.async.wait_group %0;" :: "n"(N) : "memory")

#define LDSM_X4(R, addr)                                                     \
    asm volatile("ldmatrix.sync.aligned.m8n8.x4.shared.b16 {%0,%1,%2,%3}, [%4];" \
                 : "=r"((R)[0]), "=r"((R)[1]), "=r"((R)[2]), "=r"((R)[3])    \
                 : "r"(addr))

#define MMA_F16(C, A, B0, B1)                                                \
    asm volatile("mma.sync.aligned.m16n8k16.row.col.f32.f16.f16.f32 "        \
                 "{%0,%1,%2,%3}, {%4,%5,%6,%7}, {%8,%9}, {%0,%1,%2,%3};"     \
                 : "+f"((C)[0]), "+f"((C)[1]), "+f"((C)[2]), "+f"((C)[3])    \
                 : "r"((A)[0]), "r"((A)[1]), "r"((A)[2]), "r"((A)[3]),       \
                   "r"(B0), "r"(B1))

__device__ __forceinline__ uint32_t swz(int row, int col_bytes) {
    return (uint32_t)(row * 128 + (col_bytes ^ ((row & 7) * 16)));
}

// --------------------------------------------------------------------------
// GEMM over m-tiles [mt0, mt0+grid/8): R7 champion structure, full K.
// --------------------------------------------------------------------------
__global__ void __launch_bounds__(256, 2)
gemm_f16_kernel(float* __restrict__ C, int mt0) {
    extern __shared__ uint8_t smem[];
    const uint32_t sbase = (uint32_t)__cvta_generic_to_shared(smem);

    const int tid  = threadIdx.x;
    const int lane = tid & 31;
    const int wid  = tid >> 5;
    const int wm   = (wid & 3) * 32;
    const int wn   = (wid >> 2) * 64;

    const int m0 = (mt0 + (blockIdx.x >> 3)) * BM;   // octet shares A in L2
    const int n0 = (blockIdx.x & 7) * BN;

    auto load_stage = [&](int s, int kt) {
        const uint32_t st = sbase + s * STAGE_BYTES;
        const int kbase = kt * BK;
        #pragma unroll
        for (int i = 0; i < 4; i++) {
            const int idx = tid + i * 256;
            const int row = idx >> 3;
            const int ch  = idx & 7;
            const uint32_t soff = swz(row, ch * 16);
            cp_async16(st +              soff, &g_Ah[(size_t)(m0 + row) * K_DIM + kbase + ch * 8]);
            cp_async16(st + TILE_BYTES + soff, &g_Bh[(size_t)(n0 + row) * K_DIM + kbase + ch * 8]);
        }
    };

    int a_row[2], a_xor[2];
    #pragma unroll
    for (int m = 0; m < 2; m++) {
        const int r = wm + m * 16 + (lane & 15);
        a_row[m] = r * 128;
        a_xor[m] = (r & 7) * 16;
    }
    const int a_colb = (lane >> 4) * 16;
    int b_row[4], b_xor[4];
    #pragma unroll
    for (int p = 0; p < 4; p++) {
        const int r = wn + p * 16 + (lane & 7) + ((lane >> 4) << 3);
        b_row[p] = r * 128;
        b_xor[p] = (r & 7) * 16;
    }
    const int b_colb = ((lane >> 3) & 1) * 16;

    auto lds_frags = [&](uint32_t st, int ks, uint32_t (&a)[2][4], uint32_t (&b)[4][4]) {
        const int kb = ks * 32;
        #pragma unroll
        for (int m = 0; m < 2; m++)
            LDSM_X4(a[m], st + a_row[m] + ((kb + a_colb) ^ a_xor[m]));
        #pragma unroll
        for (int p = 0; p < 4; p++)
            LDSM_X4(b[p], st + TILE_BYTES + b_row[p] + ((kb + b_colb) ^ b_xor[p]));
    };

    float acc[2][8][4];
    #pragma unroll
    for (int m = 0; m < 2; m++)
        #pragma unroll
        for (int n = 0; n < 8; n++)
            #pragma unroll
            for (int q = 0; q < 4; q++) acc[m][n][q] = 0.f;

    load_stage(0, 0); CP_COMMIT();
    load_stage(1, 1); CP_COMMIT();

    uint32_t af[2][2][4], bf[2][4][4];

    for (int kt = 0; kt < NK; kt++) {
        if (kt < NK - 1) { CP_WAIT(1); } else { CP_WAIT(0); }
        __syncthreads();
        if (kt + 2 < NK) {
            load_stage((kt + 2) % STAGES, kt + 2);
            CP_COMMIT();
        }

        const uint32_t st = sbase + (kt % STAGES) * STAGE_BYTES;

        lds_frags(st, 0, af[0], bf[0]);
        #pragma unroll
        for (int ks = 0; ks < 4; ks++) {
            const int cur = ks & 1;
            if (ks < 3)
                lds_frags(st, ks + 1, af[cur ^ 1], bf[cur ^ 1]);
            #pragma unroll
            for (int m = 0; m < 2; m++)
                #pragma unroll
                for (int p = 0; p < 4; p++)
                    #pragma unroll
                    for (int q = 0; q < 2; q++)
                        MMA_F16(acc[m][2 * p + q], af[cur][m],
                                bf[cur][p][2 * q], bf[cur][p][2 * q + 1]);
        }
    }

    #pragma unroll
    for (int m = 0; m < 2; m++) {
        const int r0 = m0 + wm + m * 16 + (lane >> 2);
        #pragma unroll
        for (int n = 0; n < 8; n++) {
            const int col = n0 + wn + n * 8 + (lane & 3) * 2;
            float2* q0 = reinterpret_cast<float2*>(&C[(size_t)r0 * N_TOTAL + col]);
            float2* q1 = reinterpret_cast<float2*>(&C[(size_t)(r0 + 8) * N_TOTAL + col]);
            *q0 = make_float2(acc[m][n][0], acc[m][n][1]);
            *q1 = make_float2(acc[m][n][2], acc[m][n][3]);
        }
    }
}

// --------------------------------------------------------------------------
// Launch: true two-stream overlap with event join (graph-capturable fork)
// --------------------------------------------------------------------------
extern "C" void kernel_launch(void* const* d_in, const int* in_sizes, int n_in,
                              void* d_out, int out_size) {
    const float* A = (const float*)d_in[0];   // [8192, 4096]
    const float* B = (const float*)d_in[1];   // [1024, 4096]
    float* C = (float*)d_out;                 // [8192, 1024]

    __half *aH, *bH;
    cudaGetSymbolAddress((void**)&aH, g_Ah);
    cudaGetSymbolAddress((void**)&bH, g_Bh);

    static cudaStream_t side = nullptr;
    static cudaEvent_t ev0 = nullptr, ev2 = nullptr;
    static bool init_done = false;
    if (!init_done) {
        cudaStreamCreateWithFlags(&side, cudaStreamNonBlocking);
        cudaEventCreateWithFlags(&ev0, cudaEventDisableTiming);
        cudaEventCreateWithFlags(&ev2, cudaEventDisableTiming);
        cudaFuncSetAttribute(gemm_f16_kernel,
                             cudaFuncAttributeMaxDynamicSharedMemorySize, SMEM_TOTAL);
        init_done = true;
    }

    // ---- main: head convert (B + A half0), then fork point ----
    {
        const int tot = NB4 + NA0_F4;
        cvt_head_kernel<<<(tot + 255) / 256, 256>>>((const float4*)A, (const float4*)B,
                                                    (uint2*)aH, (uint2*)bH);
    }
    cudaEventRecord(ev0, 0);

    // ---- side: cvt A half1, then GEMM half1 (concurrent with GEMM half0) ----
    cudaStreamWaitEvent(side, ev0, 0);
    cvt_a1_kernel<<<(NA1_F4 + 255) / 256, 256, 0, side>>>((const float4*)A, (uint2*)aH);
    gemm_f16_kernel<<<MT1 * 8, 256, SMEM_TOTAL, side>>>(C, MT0);
    cudaEventRecord(ev2, side);

    // ---- main: GEMM half0 immediately; join side stream at the end ----
    gemm_f16_kernel<<<MT0 * 8, 256, SMEM_TOTAL>>>(C, 0);
    cudaStreamWaitEvent(0, ev2, 0);
}